// round 6
// baseline (speedup 1.0000x reference)
#include <cuda_runtime.h>
#include <math.h>
#include <stdint.h>

// ---------------------------------------------------------------------------
// GraphConvolution (hyperbolic GCN layer) — tf32 tensor-core GEMM (software-
// pipelined register double buffering) + fused hyperbolic epilogue,
// float4-RED SpMM, expmap0+proj finisher.
// ---------------------------------------------------------------------------

#define MAXN  50432
#define FOUT  64
#define MIN_NORM 1e-15f
#define BALL_EPS 4e-3f

__device__ float g_tmp[MAXN * FOUT];
__device__ float g_accum[MAXN * FOUT];

__device__ __forceinline__ float warp_sum(float v) {
    #pragma unroll
    for (int o = 16; o > 0; o >>= 1) v += __shfl_xor_sync(0xffffffffu, v, o);
    return v;
}
__device__ __forceinline__ float red8(float v) {
    v += __shfl_xor_sync(0xffffffffu, v, 1);
    v += __shfl_xor_sync(0xffffffffu, v, 2);
    v += __shfl_xor_sync(0xffffffffu, v, 4);
    return v;
}
__device__ __forceinline__ float red4(float v) {
    v += __shfl_xor_sync(0xffffffffu, v, 1);
    v += __shfl_xor_sync(0xffffffffu, v, 2);
    return v;
}

__device__ __forceinline__ float tanh_fast(float x) {
    x = fminf(x, 15.0f);                   // x >= 0 in all our uses
    float e = __expf(2.0f * x);
    return (e - 1.0f) / (e + 1.0f);
}
__device__ __forceinline__ float artanh_fast(float v) {
    v = fminf(fmaxf(v, -1.0f + 1e-7f), 1.0f - 1e-7f);
    return 0.5f * __logf((1.0f + v) / (1.0f - v));
}

__device__ __forceinline__ uint32_t to_tf32(float f) {
    uint32_t r; asm("cvt.rna.tf32.f32 %0, %1;" : "=r"(r) : "f"(f)); return r;
}
__device__ __forceinline__ void mma_tf32(float4& d,
    uint32_t a0, uint32_t a1, uint32_t a2, uint32_t a3,
    uint32_t b0, uint32_t b1) {
    asm volatile(
        "mma.sync.aligned.m16n8k8.row.col.f32.tf32.tf32.f32 "
        "{%0,%1,%2,%3}, {%4,%5,%6,%7}, {%8,%9}, {%0,%1,%2,%3};"
        : "+f"(d.x), "+f"(d.y), "+f"(d.z), "+f"(d.w)
        : "r"(a0), "r"(a1), "r"(a2), "r"(a3), "r"(b0), "r"(b1));
}

// --- 1. fused tf32 GEMM + row-wise epilogues ----------------------------------
#define BM 64
#define BK 32
#define SA 68   // As[row][k] stride: frag loads conflict-free
#define SB 72   // Bs[k][n]  stride: frag loads conflict-free

__global__ void __launch_bounds__(128)
k_gemm_fused(const float* __restrict__ X, const float* __restrict__ W,
             const float* __restrict__ bias, const float* __restrict__ cp,
             int N, int IN) {
    __shared__ uint32_t As[BM * SA];
    __shared__ uint32_t Bs[BK * SB];
    __shared__ float s_xn[BM];
    __shared__ float s_hb[FOUT];
    __shared__ float s_y2;

    int tid  = threadIdx.x;                // 128 threads, 4 warps
    int lane = tid & 31;
    int wrp  = tid >> 5;
    int block_row = blockIdx.x * BM;
    int g = lane >> 2;                     // 0..7  (mma group)
    int t = lane & 3;                      // 0..3  (mma thread-in-group)
    int wrow = wrp * 16;                   // warp's 16-row slice

    float c  = cp[0];
    float sc = sqrtf(c);

    // warp 0: hyperbolic bias hb = proj(expmap0(bias, c), c) and ||hb||^2
    if (wrp == 0) {
        float u0 = bias[lane], u1 = bias[lane + 32];
        float un = fmaxf(sqrtf(warp_sum(u0 * u0 + u1 * u1)), MIN_NORM);
        float scale = tanh_fast(sc * un) / (sc * un);
        float p0 = scale * u0, p1 = scale * u1;
        float pn = fmaxf(sqrtf(warp_sum(p0 * p0 + p1 * p1)), MIN_NORM);
        float maxn = (1.0f - BALL_EPS) / sc;
        float f = (pn > maxn) ? (maxn / pn) : 1.0f;
        s_hb[lane]      = p0 * f;
        s_hb[lane + 32] = p1 * f;
        if (lane == 0) {
            float hn = fminf(pn, maxn);
            s_y2 = hn * hn;
        }
    }

    float4 acc[8];                         // warp covers 16 rows x 64 cols
    #pragma unroll
    for (int i = 0; i < 8; i++) acc[i] = make_float4(0.f, 0.f, 0.f, 0.f);

    float xsum[4] = {0.f, 0.f, 0.f, 0.f};  // fp32 ||x||^2 partials

    // register staging for software pipeline
    float4 xv[4], wv[4];

    // precomputed per-thread load coordinates
    int xr[4], xc[4], wr[4], wc[4];
    #pragma unroll
    for (int i = 0; i < 4; i++) {
        int idx = tid + i * 128;
        xr[i] = idx >> 3;  xc[i] = (idx & 7) * 4;
        wr[i] = idx >> 4;  wc[i] = (idx & 15) * 4;
    }

    // prologue: load first tiles into registers
    #pragma unroll
    for (int i = 0; i < 4; i++) {
        int gr = block_row + xr[i];
        xv[i] = (gr < N) ? *reinterpret_cast<const float4*>(X + (size_t)gr * IN + xc[i])
                         : make_float4(0.f, 0.f, 0.f, 0.f);
        wv[i] = *reinterpret_cast<const float4*>(W + (size_t)wr[i] * FOUT + wc[i]);
    }

    int ntiles = IN / BK;
    for (int it = 0; it < ntiles; it++) {
        // store staged tiles into smem (cvt to tf32), accumulate ||x||^2
        #pragma unroll
        for (int i = 0; i < 4; i++) {
            float4 v = xv[i];
            xsum[i] += v.x * v.x + v.y * v.y + v.z * v.z + v.w * v.w;
            uint32_t* a = As + xr[i] * SA + xc[i];
            a[0] = to_tf32(v.x); a[1] = to_tf32(v.y);
            a[2] = to_tf32(v.z); a[3] = to_tf32(v.w);
            float4 w = wv[i];
            uint32_t* b = Bs + wr[i] * SB + wc[i];
            b[0] = to_tf32(w.x); b[1] = to_tf32(w.y);
            b[2] = to_tf32(w.z); b[3] = to_tf32(w.w);
        }
        __syncthreads();

        // issue next tile's LDGs early — latency overlaps the MMAs below
        if (it + 1 < ntiles) {
            int k0n = (it + 1) * BK;
            #pragma unroll
            for (int i = 0; i < 4; i++) {
                int gr = block_row + xr[i];
                xv[i] = (gr < N) ? *reinterpret_cast<const float4*>(X + (size_t)gr * IN + k0n + xc[i])
                                 : make_float4(0.f, 0.f, 0.f, 0.f);
                wv[i] = *reinterpret_cast<const float4*>(W + (size_t)(k0n + wr[i]) * FOUT + wc[i]);
            }
        }

        #pragma unroll
        for (int ks = 0; ks < BK / 8; ks++) {
            int kk = ks * 8;
            uint32_t a0 = As[(wrow + g)     * SA + kk + t];
            uint32_t a1 = As[(wrow + g + 8) * SA + kk + t];
            uint32_t a2 = As[(wrow + g)     * SA + kk + t + 4];
            uint32_t a3 = As[(wrow + g + 8) * SA + kk + t + 4];
            #pragma unroll
            for (int nt = 0; nt < 8; nt++) {
                uint32_t b0 = Bs[(kk + t)     * SB + nt * 8 + g];
                uint32_t b1 = Bs[(kk + t + 4) * SB + nt * 8 + g];
                mma_tf32(acc[nt], a0, a1, a2, a3, b0, b1);
            }
        }
        __syncthreads();
    }

    // per-row ||x||: lanes sharing tid>>3 hold row (tid>>3)+16i
    #pragma unroll
    for (int i = 0; i < 4; i++) {
        float s = red8(xsum[i]);
        if ((tid & 7) == 0) s_xn[(tid >> 3) + 16 * i] = fmaxf(sqrtf(s), MIN_NORM);
    }

    // zero accumulator rows for this block
    {
        float4 z = make_float4(0.f, 0.f, 0.f, 0.f);
        float4* ab = reinterpret_cast<float4*>(g_accum + (size_t)block_row * FOUT);
        int lim4 = ((N - block_row) < BM ? (N - block_row) : BM) * FOUT / 4;
        #pragma unroll
        for (int i = 0; i < (BM * FOUT / 4) / 128; i++) {
            int idx = tid + i * 128;
            if (idx < lim4) ab[idx] = z;
        }
    }
    __syncthreads();

    // epilogue in registers. Thread owns rows (wrow+g) [.x.y] and (wrow+g+8)
    // [.z.w]; each row's 64 cols live in its 4-lane quad.
    float y2 = s_y2;
    float h0[8], h1[8];
    #pragma unroll
    for (int nt = 0; nt < 8; nt++) {
        h0[nt] = s_hb[nt * 8 + 2 * t];
        h1[nt] = s_hb[nt * 8 + 2 * t + 1];
    }

    float smx_a = 0.f, sxh_a = 0.f, smx_b = 0.f, sxh_b = 0.f;
    #pragma unroll
    for (int nt = 0; nt < 8; nt++) {
        smx_a += acc[nt].x * acc[nt].x + acc[nt].y * acc[nt].y;
        sxh_a += acc[nt].x * h0[nt]    + acc[nt].y * h1[nt];
        smx_b += acc[nt].z * acc[nt].z + acc[nt].w * acc[nt].w;
        sxh_b += acc[nt].z * h0[nt]    + acc[nt].w * h1[nt];
    }
    smx_a = red4(smx_a); sxh_a = red4(sxh_a);
    smx_b = red4(smx_b); sxh_b = red4(sxh_b);

    #pragma unroll
    for (int half = 0; half < 2; half++) {
        int r   = wrow + g + 8 * half;
        int row = block_row + r;
        float smx = half ? smx_b : smx_a;
        float sxh = half ? sxh_b : sxh_a;

        float x_n = s_xn[r];
        float mxn = fmaxf(sqrtf(smx), MIN_NORM);
        float at  = artanh_fast(sc * x_n);
        float scl = tanh_fast(mxn / x_n * at) / (mxn * sc);
        if (smx == 0.0f) scl = 0.0f;

        float x2 = scl * scl * smx;        // ||res||^2
        float xy = scl * sxh;              // res . hb

        float A = 1.0f + 2.0f * c * xy + c * y2;
        float B = 1.0f - c * x2;
        float den = fmaxf(1.0f + 2.0f * c * xy + c * c * x2 * y2, MIN_NORM);
        float inv_den = 1.0f / den;

        float a0[8], a1[8], pa = 0.f;
        #pragma unroll
        for (int nt = 0; nt < 8; nt++) {
            float m0 = half ? acc[nt].z : acc[nt].x;
            float m1 = half ? acc[nt].w : acc[nt].y;
            a0[nt] = (A * (scl * m0) + B * h0[nt]) * inv_den;
            a1[nt] = (A * (scl * m1) + B * h1[nt]) * inv_den;
            pa += a0[nt] * a0[nt] + a1[nt] * a1[nt];
        }
        pa = red4(pa);
        float pn = fmaxf(sqrtf(pa), MIN_NORM);
        float tt = artanh_fast(sc * pn) / (sc * pn);

        if (row < N) {
            float* dst = g_tmp + (size_t)row * FOUT + 2 * t;
            #pragma unroll
            for (int nt = 0; nt < 8; nt++)
                *reinterpret_cast<float2*>(dst + nt * 8) = make_float2(tt * a0[nt], tt * a1[nt]);
        }
    }
}

// --- 2. SpMM: accum[row[e]] += vals[e] * tmp[col[e]] --------------------------
__global__ void k_spmm(const float* __restrict__ vals, const int* __restrict__ row,
                       const int* __restrict__ col, int E) {
    int g = blockIdx.x * blockDim.x + threadIdx.x;
    int e = g >> 4;
    int lane = g & 15;
    if (e >= E) return;
    int cc = __ldg(col + e);
    int rr = __ldg(row + e);
    float v = __ldg(vals + e);
    float4 t = *reinterpret_cast<const float4*>(g_tmp + (size_t)cc * FOUT + lane * 4);
    float4 a = make_float4(t.x * v, t.y * v, t.z * v, t.w * v);
    atomicAdd(reinterpret_cast<float4*>(g_accum + (size_t)rr * FOUT) + lane, a);
}

// --- 3. final: out = proj(expmap0(accum)) ------------------------------------
__global__ void k_final(const float* __restrict__ cp, float* __restrict__ out, int N) {
    int warp = (blockIdx.x * blockDim.x + threadIdx.x) >> 5;
    int lane = threadIdx.x & 31;
    if (warp >= N) return;
    float c = cp[0];
    float sc = sqrtf(c);
    size_t base = (size_t)warp * FOUT;
    float u0 = g_accum[base + lane];
    float u1 = g_accum[base + lane + 32];
    float un = fmaxf(sqrtf(warp_sum(u0 * u0 + u1 * u1)), MIN_NORM);
    float scale = tanh_fast(sc * un) / (sc * un);
    float p0 = scale * u0, p1 = scale * u1;
    float pn = fmaxf(sqrtf(warp_sum(p0 * p0 + p1 * p1)), MIN_NORM);
    float maxn = (1.0f - BALL_EPS) / sc;
    float f = (pn > maxn) ? (maxn / pn) : 1.0f;
    out[base + lane]      = p0 * f;
    out[base + lane + 32] = p1 * f;
}

// ---------------------------------------------------------------------------

extern "C" void kernel_launch(void* const* d_in, const int* in_sizes, int n_in,
                              void* d_out, int out_size) {
    const float* x    = (const float*)d_in[0];
    const float* w    = (const float*)d_in[1];
    const float* bias = (const float*)d_in[2];
    const float* vals = (const float*)d_in[3];
    const float* c    = (const float*)d_in[4];
    const int*   row  = (const int*)d_in[5];
    const int*   col  = (const int*)d_in[6];
    float* out = (float*)d_out;

    int OUT = in_sizes[2];               // 64
    int IN  = in_sizes[1] / OUT;         // 256
    int N   = in_sizes[0] / IN;          // 50000
    int E   = in_sizes[3];               // 800000
    (void)OUT; (void)n_in; (void)out_size;

    // 1. fused tf32 GEMM + epilogues (+ accumulator zeroing)
    k_gemm_fused<<<(N + BM - 1) / BM, 128>>>(x, w, bias, c, N, IN);

    // 2. SpMM scatter-add
    long long tot = (long long)E * 16;
    k_spmm<<<(int)((tot + 255) / 256), 256>>>(vals, row, col, E);

    // 3. final expmap0 + proj
    int rowBlocks = (N + 7) / 8;
    k_final<<<rowBlocks, 256>>>(c, out, N);
}

// round 7
// speedup vs baseline: 1.3094x; 1.3094x over previous
#include <cuda_runtime.h>
#include <cuda_fp16.h>
#include <math.h>
#include <stdint.h>

// ---------------------------------------------------------------------------
// GraphConvolution (hyperbolic GCN layer) — tf32 tensor-core GEMM + fused
// hyperbolic epilogue (writes fp16 tmp), fp16-gather/fp32-RED SpMM,
// expmap0+proj finisher.
// ---------------------------------------------------------------------------

#define MAXN  50432
#define FOUT  64
#define MIN_NORM 1e-15f
#define BALL_EPS 4e-3f

__device__ __half g_tmph[MAXN * FOUT];   // logmap0 output, fp16
__device__ float  g_accum[MAXN * FOUT];  // segment-sum accumulator, fp32

__device__ __forceinline__ float warp_sum(float v) {
    #pragma unroll
    for (int o = 16; o > 0; o >>= 1) v += __shfl_xor_sync(0xffffffffu, v, o);
    return v;
}
__device__ __forceinline__ float red8(float v) {
    v += __shfl_xor_sync(0xffffffffu, v, 1);
    v += __shfl_xor_sync(0xffffffffu, v, 2);
    v += __shfl_xor_sync(0xffffffffu, v, 4);
    return v;
}
__device__ __forceinline__ float red4(float v) {
    v += __shfl_xor_sync(0xffffffffu, v, 1);
    v += __shfl_xor_sync(0xffffffffu, v, 2);
    return v;
}

__device__ __forceinline__ float tanh_fast(float x) {
    x = fminf(x, 15.0f);                   // x >= 0 in all our uses
    float e = __expf(2.0f * x);
    return (e - 1.0f) / (e + 1.0f);
}
__device__ __forceinline__ float artanh_fast(float v) {
    v = fminf(fmaxf(v, -1.0f + 1e-7f), 1.0f - 1e-7f);
    return 0.5f * __logf((1.0f + v) / (1.0f - v));
}

__device__ __forceinline__ uint32_t to_tf32(float f) {
    uint32_t r; asm("cvt.rna.tf32.f32 %0, %1;" : "=r"(r) : "f"(f)); return r;
}
__device__ __forceinline__ void mma_tf32(float4& d,
    uint32_t a0, uint32_t a1, uint32_t a2, uint32_t a3,
    uint32_t b0, uint32_t b1) {
    asm volatile(
        "mma.sync.aligned.m16n8k8.row.col.f32.tf32.tf32.f32 "
        "{%0,%1,%2,%3}, {%4,%5,%6,%7}, {%8,%9}, {%0,%1,%2,%3};"
        : "+f"(d.x), "+f"(d.y), "+f"(d.z), "+f"(d.w)
        : "r"(a0), "r"(a1), "r"(a2), "r"(a3), "r"(b0), "r"(b1));
}

// --- 1. fused tf32 GEMM + row-wise epilogues (exact R5 mainloop) --------------
#define BM 64
#define BK 32
#define SA 68   // As[row][k] stride: frag loads conflict-free
#define SB 72   // Bs[k][n]  stride: frag loads conflict-free

__global__ void __launch_bounds__(128)
k_gemm_fused(const float* __restrict__ X, const float* __restrict__ W,
             const float* __restrict__ bias, const float* __restrict__ cp,
             int N, int IN) {
    __shared__ uint32_t As[BM * SA];
    __shared__ uint32_t Bs[BK * SB];
    __shared__ float s_xn[BM];
    __shared__ float s_hb[FOUT];
    __shared__ float s_y2;

    int tid  = threadIdx.x;                // 128 threads, 4 warps
    int lane = tid & 31;
    int wrp  = tid >> 5;
    int block_row = blockIdx.x * BM;
    int g = lane >> 2;                     // 0..7  (mma group)
    int t = lane & 3;                      // 0..3  (mma thread-in-group)
    int wrow = wrp * 16;                   // warp's 16-row slice

    float c  = cp[0];
    float sc = sqrtf(c);

    // warp 0: hyperbolic bias hb = proj(expmap0(bias, c), c) and ||hb||^2
    if (wrp == 0) {
        float u0 = bias[lane], u1 = bias[lane + 32];
        float un = fmaxf(sqrtf(warp_sum(u0 * u0 + u1 * u1)), MIN_NORM);
        float scale = tanh_fast(sc * un) / (sc * un);
        float p0 = scale * u0, p1 = scale * u1;
        float pn = fmaxf(sqrtf(warp_sum(p0 * p0 + p1 * p1)), MIN_NORM);
        float maxn = (1.0f - BALL_EPS) / sc;
        float f = (pn > maxn) ? (maxn / pn) : 1.0f;
        s_hb[lane]      = p0 * f;
        s_hb[lane + 32] = p1 * f;
        if (lane == 0) {
            float hn = fminf(pn, maxn);
            s_y2 = hn * hn;
        }
    }

    float4 acc[8];                         // warp covers 16 rows x 64 cols
    #pragma unroll
    for (int i = 0; i < 8; i++) acc[i] = make_float4(0.f, 0.f, 0.f, 0.f);

    float xsum[4] = {0.f, 0.f, 0.f, 0.f};  // fp32 ||x||^2 partials

    for (int k0 = 0; k0 < IN; k0 += BK) {
        // X tile: 64 rows x 32 k  (512 float4, 4/thread)
        #pragma unroll
        for (int i = 0; i < 4; i++) {
            int idx = tid + i * 128;
            int r   = idx >> 3;            // 0..63
            int c4  = idx & 7;
            int gr  = block_row + r;
            float4 v = (gr < N) ? *reinterpret_cast<const float4*>(X + (size_t)gr * IN + k0 + c4 * 4)
                                : make_float4(0.f, 0.f, 0.f, 0.f);
            xsum[i] += v.x * v.x + v.y * v.y + v.z * v.z + v.w * v.w;
            uint32_t* a = As + r * SA + c4 * 4;
            a[0] = to_tf32(v.x); a[1] = to_tf32(v.y);
            a[2] = to_tf32(v.z); a[3] = to_tf32(v.w);
        }
        // W tile: 32 k x 64 n
        #pragma unroll
        for (int i = 0; i < 4; i++) {
            int idx = tid + i * 128;
            int r   = idx >> 4;            // 0..31
            int c4  = idx & 15;
            float4 v = *reinterpret_cast<const float4*>(W + (size_t)(k0 + r) * FOUT + c4 * 4);
            uint32_t* b = Bs + r * SB + c4 * 4;
            b[0] = to_tf32(v.x); b[1] = to_tf32(v.y);
            b[2] = to_tf32(v.z); b[3] = to_tf32(v.w);
        }
        __syncthreads();

        #pragma unroll
        for (int ks = 0; ks < BK / 8; ks++) {
            int kk = ks * 8;
            uint32_t a0 = As[(wrow + g)     * SA + kk + t];
            uint32_t a1 = As[(wrow + g + 8) * SA + kk + t];
            uint32_t a2 = As[(wrow + g)     * SA + kk + t + 4];
            uint32_t a3 = As[(wrow + g + 8) * SA + kk + t + 4];
            #pragma unroll
            for (int nt = 0; nt < 8; nt++) {
                uint32_t b0 = Bs[(kk + t)     * SB + nt * 8 + g];
                uint32_t b1 = Bs[(kk + t + 4) * SB + nt * 8 + g];
                mma_tf32(acc[nt], a0, a1, a2, a3, b0, b1);
            }
        }
        __syncthreads();
    }

    // per-row ||x||: lanes sharing tid>>3 hold row (tid>>3)+16i
    #pragma unroll
    for (int i = 0; i < 4; i++) {
        float s = red8(xsum[i]);
        if ((tid & 7) == 0) s_xn[(tid >> 3) + 16 * i] = fmaxf(sqrtf(s), MIN_NORM);
    }

    // zero accumulator rows for this block
    {
        float4 z = make_float4(0.f, 0.f, 0.f, 0.f);
        float4* ab = reinterpret_cast<float4*>(g_accum + (size_t)block_row * FOUT);
        int lim4 = ((N - block_row) < BM ? (N - block_row) : BM) * FOUT / 4;
        #pragma unroll
        for (int i = 0; i < (BM * FOUT / 4) / 128; i++) {
            int idx = tid + i * 128;
            if (idx < lim4) ab[idx] = z;
        }
    }
    __syncthreads();

    // epilogue in registers. Thread owns rows (wrow+g) [.x.y] and (wrow+g+8)
    // [.z.w]; each row's 64 cols live in its 4-lane quad.
    float y2 = s_y2;
    float h0[8], h1[8];
    #pragma unroll
    for (int nt = 0; nt < 8; nt++) {
        h0[nt] = s_hb[nt * 8 + 2 * t];
        h1[nt] = s_hb[nt * 8 + 2 * t + 1];
    }

    float smx_a = 0.f, sxh_a = 0.f, smx_b = 0.f, sxh_b = 0.f;
    #pragma unroll
    for (int nt = 0; nt < 8; nt++) {
        smx_a += acc[nt].x * acc[nt].x + acc[nt].y * acc[nt].y;
        sxh_a += acc[nt].x * h0[nt]    + acc[nt].y * h1[nt];
        smx_b += acc[nt].z * acc[nt].z + acc[nt].w * acc[nt].w;
        sxh_b += acc[nt].z * h0[nt]    + acc[nt].w * h1[nt];
    }
    smx_a = red4(smx_a); sxh_a = red4(sxh_a);
    smx_b = red4(smx_b); sxh_b = red4(sxh_b);

    #pragma unroll
    for (int half = 0; half < 2; half++) {
        int r   = wrow + g + 8 * half;
        int row = block_row + r;
        float smx = half ? smx_b : smx_a;
        float sxh = half ? sxh_b : sxh_a;

        float x_n = s_xn[r];
        float mxn = fmaxf(sqrtf(smx), MIN_NORM);
        float at  = artanh_fast(sc * x_n);
        float scl = tanh_fast(mxn / x_n * at) / (mxn * sc);
        if (smx == 0.0f) scl = 0.0f;

        float x2 = scl * scl * smx;        // ||res||^2
        float xy = scl * sxh;              // res . hb

        float A = 1.0f + 2.0f * c * xy + c * y2;
        float B = 1.0f - c * x2;
        float den = fmaxf(1.0f + 2.0f * c * xy + c * c * x2 * y2, MIN_NORM);
        float inv_den = 1.0f / den;

        float a0[8], a1[8], pa = 0.f;
        #pragma unroll
        for (int nt = 0; nt < 8; nt++) {
            float m0 = half ? acc[nt].z : acc[nt].x;
            float m1 = half ? acc[nt].w : acc[nt].y;
            a0[nt] = (A * (scl * m0) + B * h0[nt]) * inv_den;
            a1[nt] = (A * (scl * m1) + B * h1[nt]) * inv_den;
            pa += a0[nt] * a0[nt] + a1[nt] * a1[nt];
        }
        pa = red4(pa);
        float pn = fmaxf(sqrtf(pa), MIN_NORM);
        float tt = artanh_fast(sc * pn) / (sc * pn);

        if (row < N) {
            __half2* dst = reinterpret_cast<__half2*>(g_tmph + (size_t)row * FOUT + 2 * t);
            #pragma unroll
            for (int nt = 0; nt < 8; nt++)
                dst[nt * 4] = __floats2half2_rn(tt * a0[nt], tt * a1[nt]);
        }
    }
}

// --- 2. SpMM: accum[row[e]] += vals[e] * tmph[col[e]]  (fp16 gather) ----------
// 16 lanes/edge; each lane reads 4 halves (8B), converts, one float4 RED.
__global__ void k_spmm(const float* __restrict__ vals, const int* __restrict__ row,
                       const int* __restrict__ col, int E) {
    int g = blockIdx.x * blockDim.x + threadIdx.x;
    int e = g >> 4;
    int lane = g & 15;
    if (e >= E) return;
    int cc = __ldg(col + e);
    int rr = __ldg(row + e);
    float v = __ldg(vals + e);
    const __half2* src = reinterpret_cast<const __half2*>(g_tmph + (size_t)cc * FOUT + lane * 4);
    __half2 t01 = src[0];
    __half2 t23 = src[1];
    float2 f01 = __half22float2(t01);
    float2 f23 = __half22float2(t23);
    float4 a = make_float4(f01.x * v, f01.y * v, f23.x * v, f23.y * v);
    atomicAdd(reinterpret_cast<float4*>(g_accum + (size_t)rr * FOUT) + lane, a);
}

// --- 3. final: out = proj(expmap0(accum)) ------------------------------------
__global__ void k_final(const float* __restrict__ cp, float* __restrict__ out, int N) {
    int warp = (blockIdx.x * blockDim.x + threadIdx.x) >> 5;
    int lane = threadIdx.x & 31;
    if (warp >= N) return;
    float c = cp[0];
    float sc = sqrtf(c);
    size_t base = (size_t)warp * FOUT;
    float u0 = g_accum[base + lane];
    float u1 = g_accum[base + lane + 32];
    float un = fmaxf(sqrtf(warp_sum(u0 * u0 + u1 * u1)), MIN_NORM);
    float scale = tanh_fast(sc * un) / (sc * un);
    float p0 = scale * u0, p1 = scale * u1;
    float pn = fmaxf(sqrtf(warp_sum(p0 * p0 + p1 * p1)), MIN_NORM);
    float maxn = (1.0f - BALL_EPS) / sc;
    float f = (pn > maxn) ? (maxn / pn) : 1.0f;
    out[base + lane]      = p0 * f;
    out[base + lane + 32] = p1 * f;
}

// ---------------------------------------------------------------------------

extern "C" void kernel_launch(void* const* d_in, const int* in_sizes, int n_in,
                              void* d_out, int out_size) {
    const float* x    = (const float*)d_in[0];
    const float* w    = (const float*)d_in[1];
    const float* bias = (const float*)d_in[2];
    const float* vals = (const float*)d_in[3];
    const float* c    = (const float*)d_in[4];
    const int*   row  = (const int*)d_in[5];
    const int*   col  = (const int*)d_in[6];
    float* out = (float*)d_out;

    int OUT = in_sizes[2];               // 64
    int IN  = in_sizes[1] / OUT;         // 256
    int N   = in_sizes[0] / IN;          // 50000
    int E   = in_sizes[3];               // 800000
    (void)OUT; (void)n_in; (void)out_size;

    // 1. fused tf32 GEMM + epilogues (+ accumulator zeroing)
    k_gemm_fused<<<(N + BM - 1) / BM, 128>>>(x, w, bias, c, N, IN);

    // 2. SpMM scatter-add (fp16 gather, fp32 RED)
    long long tot = (long long)E * 16;
    k_spmm<<<(int)((tot + 255) / 256), 256>>>(vals, row, col, E);

    // 3. final expmap0 + proj
    int rowBlocks = (N + 7) / 8;
    k_final<<<rowBlocks, 256>>>(c, out, N);
}